// round 5
// baseline (speedup 1.0000x reference)
#include <cuda_runtime.h>

#define WS   11
#define TILE 32
#define IN   42
#define NC   48

typedef unsigned long long u64;

// ---------------- packed f32x2 helpers --------------------------------------
__device__ __forceinline__ u64 pack2(float lo, float hi) {
    u64 r; asm("mov.b64 %0, {%1, %2};" : "=l"(r) : "f"(lo), "f"(hi)); return r;
}
__device__ __forceinline__ float2 unpack2(u64 v) {
    float2 f; asm("mov.b64 {%0, %1}, %2;" : "=f"(f.x), "=f"(f.y) : "l"(v)); return f;
}
__device__ __forceinline__ u64 fma2(u64 a, u64 b, u64 c) {
    u64 d; asm("fma.rn.f32x2 %0, %1, %2, %3;" : "=l"(d) : "l"(a), "l"(b), "l"(c)); return d;
}
__device__ __forceinline__ u64 add2(u64 a, u64 b) {
    u64 d; asm("add.rn.f32x2 %0, %1, %2;" : "=l"(d) : "l"(a), "l"(b)); return d;
}
__device__ __forceinline__ u64 mul2(u64 a, u64 b) {
    u64 d; asm("mul.rn.f32x2 %0, %1, %2;" : "=l"(d) : "l"(a), "l"(b)); return d;
}

// ---------------- scratch ----------------------------------------------------
__device__ float g_cs_sum[5][NC];
__device__ float g_ssim_sum[5][NC];
__device__ u64 g_s1[NC * 256 * 256];   // interleaved (x,y)
__device__ u64 g_s2[NC * 128 * 128];
__device__ u64 g_s3[NC * 64 * 64];
__device__ u64 g_s4[NC * 32 * 32];

__global__ void init_kernel() {
    int t = threadIdx.x;
    if (t < 5 * NC) { (&g_cs_sum[0][0])[t] = 0.f; (&g_ssim_sum[0][0])[t] = 0.f; }
}

// ======== ssim core pieces ===================================================
#define SSIM_SHARED \
    __shared__ u64 sA[IN][IN + 1]; \
    __shared__ u64 h1[IN][TILE + 1]; \
    __shared__ u64 h2[IN][TILE + 1]; \
    __shared__ float tg_s[WS]; \
    __shared__ float red[16];

#define SSIM_TAPS \
    if (tid < WS) tg_s[tid] = win[tid * WS + 5] * rsqrtf(win[5 * WS + 5]);

// symmetric taps: w[k] == w[10-k]; store 6 packed entries
#define SSIM_WP \
    u64 wp[6]; \
    _Pragma("unroll") \
    for (int k = 0; k < 6; k++) { float w = tg_s[k]; wp[k] = pack2(w, w); }

#define WSYM(k) wp[(k) < 6 ? (k) : 10 - (k)]

// horizontal: 168 threads, each 8 consecutive cols from 18 sliding reads
#define SSIM_HORIZ \
    if (tid < 168) { \
        int c0g = tid / 42; \
        int r   = tid - c0g * 42; \
        int c0  = c0g * 8; \
        u64 a1v[8] = {0,0,0,0,0,0,0,0}, a2v[8] = {0,0,0,0,0,0,0,0}; \
        _Pragma("unroll") \
        for (int j = 0; j < 18; j++) { \
            u64 a = sA[r][c0 + j]; \
            float2 v = unpack2(a); \
            u64 q = pack2(fmaf(v.x, v.x, v.y * v.y), v.x * v.y); \
            _Pragma("unroll") \
            for (int o = 0; o < 8; o++) { \
                int k = j - o; \
                if (k >= 0 && k < WS) { \
                    a1v[o] = fma2(WSYM(k), a, a1v[o]); \
                    a2v[o] = fma2(WSYM(k), q, a2v[o]); \
                } \
            } \
        } \
        _Pragma("unroll") \
        for (int o = 0; o < 8; o++) { h1[r][c0 + o] = a1v[o]; h2[r][c0 + o] = a2v[o]; } \
    }

// vertical: 128 threads (warps 0-3), each col strip of 8 output rows
#define SSIM_VERT_AND_REDUCE(OVAL, SCALE) \
    float ssim_acc = 0.f, cs_acc = 0.f; \
    if (threadIdx.y < 4) { \
        int c = threadIdx.x; \
        int rbase = threadIdx.y * 8; \
        u64 a1v[8] = {0,0,0,0,0,0,0,0}, a2v[8] = {0,0,0,0,0,0,0,0}; \
        _Pragma("unroll") \
        for (int j = 0; j < 18; j++) { \
            u64 a = h1[rbase + j][c]; \
            u64 q = h2[rbase + j][c]; \
            _Pragma("unroll") \
            for (int o = 0; o < 8; o++) { \
                int k = j - o; \
                if (k >= 0 && k < WS) { \
                    a1v[o] = fma2(WSYM(k), a, a1v[o]); \
                    a2v[o] = fma2(WSYM(k), q, a2v[o]); \
                } \
            } \
        } \
        bool colv = (ox0 + c) < (OVAL); \
        _Pragma("unroll") \
        for (int o = 0; o < 8; o++) { \
            if (colv && (oy0 + rbase + o) < (OVAL)) { \
                float2 m = unpack2(a1v[o]); \
                float2 e = unpack2(a2v[o]); \
                float mxx = m.x * m.x, myy = m.y * m.y, mxy = m.x * m.y; \
                float svar = e.x - mxx - myy; \
                float sxy_ = e.y - mxy; \
                const float C1 = 1e-4f, C2 = 9e-4f; \
                float cs = __fdividef(2.f * sxy_ + C2, svar + C2); \
                float ss = __fdividef(2.f * mxy + C1, mxx + myy + C1) * cs; \
                cs_acc += cs; ssim_acc += ss; \
            } \
        } \
    } \
    _Pragma("unroll") \
    for (int o = 16; o > 0; o >>= 1) { \
        ssim_acc += __shfl_down_sync(0xffffffffu, ssim_acc, o); \
        cs_acc   += __shfl_down_sync(0xffffffffu, cs_acc, o); \
    } \
    if (threadIdx.x == 0) { red[threadIdx.y] = ssim_acc; red[8 + threadIdx.y] = cs_acc; } \
    __syncthreads(); \
    if (tid == 0) { \
        float s = 0.f, cc = 0.f; \
        _Pragma("unroll") \
        for (int i = 0; i < 8; i++) { s += red[i]; cc += red[8 + i]; } \
        atomicAdd(&g_ssim_sum[SCALE][nc], s); \
        atomicAdd(&g_cs_sum[SCALE][nc], cc); \
    }

// ======== scale 0: ssim + pooled emission into g_s1 =========================
__global__ __launch_bounds__(256) void ssim_scale0(
    const float* __restrict__ x0, const float* __restrict__ y0,
    const float* __restrict__ win) {
    SSIM_SHARED
    int b = blockIdx.x;
    int nc = b >> 8;
    int r0 = b & 255;
    int by = r0 >> 4, bx = r0 & 15;
    const float* xb = x0 + (size_t)nc * 262144;
    const float* yb = y0 + (size_t)nc * 262144;
    int ox0 = bx * 32, oy0 = by * 32;
    int tid = threadIdx.y * 32 + threadIdx.x;

    SSIM_TAPS

    for (int idx = tid; idx < IN * IN; idx += 256) {
        int r = idx / IN, c = idx - r * IN;
        int gy = oy0 + r, gx = ox0 + c;
        float xv = 0.f, yv = 0.f;
        if (gy < 512 && gx < 512) { xv = xb[gy * 512 + gx]; yv = yb[gy * 512 + gx]; }
        sA[r][c] = pack2(xv, yv);
    }
    __syncthreads();

    SSIM_WP
    SSIM_HORIZ

    // pooled emission: owned 32x32 -> 16x16 of scale-1 (reads stable sA)
    {
        int i = tid >> 4, j = tid & 15;
        u64 s = add2(add2(sA[2*i][2*j], sA[2*i][2*j+1]),
                     add2(sA[2*i+1][2*j], sA[2*i+1][2*j+1]));
        s = mul2(s, pack2(0.25f, 0.25f));
        g_s1[(size_t)nc * 65536 + (size_t)(by * 16 + i) * 256 + (bx * 16 + j)] = s;
    }
    __syncthreads();

    SSIM_VERT_AND_REDUCE(502, 0)
}

// ======== scales 1-4 =========================================================
__global__ __launch_bounds__(256) void ssim_rest(const float* __restrict__ win) {
    SSIM_SHARED
    int b = blockIdx.x;
    int D, O, nc, bx, by, scale;
    const u64* src;
    if (b < 3072)      { scale = 1; D = 256; O = 246; int l = b;        nc = l >> 6; int r = l & 63; by = r >> 3; bx = r & 7; src = g_s1; }
    else if (b < 3840) { scale = 2; D = 128; O = 118; int l = b - 3072; nc = l >> 4; int r = l & 15; by = r >> 2; bx = r & 3; src = g_s2; }
    else if (b < 4032) { scale = 3; D = 64;  O = 54;  int l = b - 3840; nc = l >> 2; int r = l & 3;  by = r >> 1; bx = r & 1; src = g_s3; }
    else               { scale = 4; D = 32;  O = 22;  int l = b - 4032; nc = l;      by = 0;         bx = 0;      src = g_s4; }
    src += (size_t)nc * D * D;
    int ox0 = bx * 32, oy0 = by * 32;
    int tid = threadIdx.y * 32 + threadIdx.x;

    SSIM_TAPS

    for (int idx = tid; idx < IN * IN; idx += 256) {
        int r = idx / IN, c = idx - r * IN;
        int gy = oy0 + r, gx = ox0 + c;
        sA[r][c] = (gy < D && gx < D) ? src[gy * D + gx] : 0ull;
    }
    __syncthreads();

    SSIM_WP
    SSIM_HORIZ
    __syncthreads();

    SSIM_VERT_AND_REDUCE(O, scale)
}

// ======== pool chain: s1 -> s2,s3,s4 =========================================
__global__ __launch_bounds__(256) void pool_rest() {
    __shared__ u64 s2s[32][33];
    __shared__ u64 s3s[16][17];
    int tid = threadIdx.x;
    int b = blockIdx.x;
    int nc = b >> 4;
    int r = b & 15;
    int by = r >> 2, bx = r & 3;
    const u64* s1 = g_s1 + (size_t)nc * 65536;
    u64 quarter = pack2(0.25f, 0.25f);
#pragma unroll
    for (int t = 0; t < 4; t++) {
        int o = tid + t * 256;
        int i = o >> 5, j = o & 31;
        int gr = by * 64 + 2 * i, gc = bx * 64 + 2 * j;
        u64 v = mul2(add2(add2(s1[gr * 256 + gc], s1[gr * 256 + gc + 1]),
                          add2(s1[(gr + 1) * 256 + gc], s1[(gr + 1) * 256 + gc + 1])), quarter);
        s2s[i][j] = v;
        g_s2[(size_t)nc * 16384 + (size_t)(by * 32 + i) * 128 + (bx * 32 + j)] = v;
    }
    __syncthreads();
    {
        int i = tid >> 4, j = tid & 15;
        u64 v = mul2(add2(add2(s2s[2*i][2*j], s2s[2*i][2*j+1]),
                          add2(s2s[2*i+1][2*j], s2s[2*i+1][2*j+1])), quarter);
        s3s[i][j] = v;
        g_s3[(size_t)nc * 4096 + (size_t)(by * 16 + i) * 64 + (bx * 16 + j)] = v;
    }
    __syncthreads();
    if (tid < 64) {
        int i = tid >> 3, j = tid & 7;
        u64 v = mul2(add2(add2(s3s[2*i][2*j], s3s[2*i][2*j+1]),
                          add2(s3s[2*i+1][2*j], s3s[2*i+1][2*j+1])), quarter);
        g_s4[(size_t)nc * 1024 + (size_t)(by * 8 + i) * 32 + (bx * 8 + j)] = v;
    }
}

// ---------------- final ------------------------------------------------------
__global__ void final_kernel(const float* __restrict__ weights, float* __restrict__ out) {
    __shared__ float vals[NC];
    int t = threadIdx.x;
    const int Os[5] = {502, 246, 118, 54, 22};
    if (t < NC) {
        float prod = 1.f;
#pragma unroll
        for (int s = 0; s < 5; s++) {
            float inv = 1.f / ((float)Os[s] * (float)Os[s]);
            float m = (s < 4) ? g_cs_sum[s][t] : g_ssim_sum[s][t];
            m *= inv;
            if (s < 4) m = fmaxf(m, 0.f);
            prod *= powf(m, weights[s]);
        }
        vals[t] = prod;
    }
    __syncthreads();
    if (t == 0) {
        float s = 0.f;
        for (int i = 0; i < NC; i++) s += vals[i];
        out[0] = s / (float)NC;
    }
}

// ---------------- launch -----------------------------------------------------
extern "C" void kernel_launch(void* const* d_in, const int* in_sizes, int n_in,
                              void* d_out, int out_size) {
    const float* x   = (const float*)d_in[0];
    const float* y   = (const float*)d_in[1];
    const float* win = (const float*)d_in[2];
    const float* wts = (const float*)d_in[3];
    float* out = (float*)d_out;

    init_kernel<<<1, 256>>>();
    ssim_scale0<<<12288, dim3(32, 8)>>>(x, y, win);
    pool_rest<<<768, 256>>>();
    ssim_rest<<<4080, dim3(32, 8)>>>(win);
    final_kernel<<<1, 64>>>(wts, out);
}

// round 6
// speedup vs baseline: 1.1458x; 1.1458x over previous
#include <cuda_runtime.h>

#define WS    11
#define TILE  32
#define IN    42
#define SAPAD 46
#define NC    48

typedef unsigned long long u64;

// ---------------- packed f32x2 helpers --------------------------------------
__device__ __forceinline__ u64 pack2(float lo, float hi) {
    u64 r; asm("mov.b64 %0, {%1, %2};" : "=l"(r) : "f"(lo), "f"(hi)); return r;
}
__device__ __forceinline__ float2 unpack2(u64 v) {
    float2 f; asm("mov.b64 {%0, %1}, %2;" : "=f"(f.x), "=f"(f.y) : "l"(v)); return f;
}
__device__ __forceinline__ u64 fma2(u64 a, u64 b, u64 c) {
    u64 d; asm("fma.rn.f32x2 %0, %1, %2, %3;" : "=l"(d) : "l"(a), "l"(b), "l"(c)); return d;
}
__device__ __forceinline__ u64 add2(u64 a, u64 b) {
    u64 d; asm("add.rn.f32x2 %0, %1, %2;" : "=l"(d) : "l"(a), "l"(b)); return d;
}
__device__ __forceinline__ u64 mul2(u64 a, u64 b) {
    u64 d; asm("mul.rn.f32x2 %0, %1, %2;" : "=l"(d) : "l"(a), "l"(b)); return d;
}

// ---------------- scratch ----------------------------------------------------
__device__ float g_cs_sum[5][NC];
__device__ float g_ssim_sum[5][NC];
__device__ u64 g_s1[NC * 256 * 256];   // interleaved (x,y)
__device__ u64 g_s2[NC * 128 * 128];
__device__ u64 g_s3[NC * 64 * 64];
__device__ u64 g_s4[NC * 32 * 32];

__global__ void init_kernel() {
    int t = threadIdx.x;
    if (t < 5 * NC) { (&g_cs_sum[0][0])[t] = 0.f; (&g_ssim_sum[0][0])[t] = 0.f; }
}

// ======== ssim core pieces ===================================================
#define SSIM_SHARED \
    __shared__ __align__(16) u64 sA[IN][SAPAD]; \
    __shared__ __align__(16) ulonglong2 hC[IN][TILE + 1]; \
    __shared__ float tg_s[WS]; \
    __shared__ float red[16];

#define SSIM_TAPS \
    if (tid < WS) tg_s[tid] = win[tid * WS + 5] * rsqrtf(win[5 * WS + 5]);

// symmetric taps: w[k] == w[10-k]
#define SSIM_WP \
    u64 wp[6]; \
    _Pragma("unroll") \
    for (int k = 0; k < 6; k++) { float w = tg_s[k]; wp[k] = pack2(w, w); }

#define WSYM(k) wp[(k) < 6 ? (k) : 10 - (k)]

// horizontal: tasks t in [0,336): r = t%42, c0 = (t/42)*4; 7 LDS.128 -> 4 outputs
#define SSIM_HORIZ \
    for (int t = tid; t < 336; t += 256) { \
        int c0g = t / 42; \
        int r   = t - c0g * 42; \
        int c0  = c0g * 4; \
        u64 a1v[4] = {0,0,0,0}, a2v[4] = {0,0,0,0}; \
        const ulonglong2* rowp = (const ulonglong2*)&sA[r][0]; \
        _Pragma("unroll") \
        for (int jp = 0; jp < 7; jp++) { \
            ulonglong2 pr = rowp[(c0 >> 1) + jp]; \
            _Pragma("unroll") \
            for (int e = 0; e < 2; e++) { \
                int j = 2 * jp + e; \
                u64 a = e ? pr.y : pr.x; \
                float2 v = unpack2(a); \
                u64 q = pack2(fmaf(v.x, v.x, v.y * v.y), v.x * v.y); \
                _Pragma("unroll") \
                for (int o = 0; o < 4; o++) { \
                    int k = j - o; \
                    if (k >= 0 && k < WS) { \
                        a1v[o] = fma2(WSYM(k), a, a1v[o]); \
                        a2v[o] = fma2(WSYM(k), q, a2v[o]); \
                    } \
                } \
            } \
        } \
        _Pragma("unroll") \
        for (int o = 0; o < 4; o++) hC[r][c0 + o] = make_ulonglong2(a1v[o], a2v[o]); \
    }

// vertical: all 256 threads, 4 output rows each; 14 LDS.128
#define SSIM_VERT_AND_REDUCE(OVAL, SCALE) \
    float ssim_acc = 0.f, cs_acc = 0.f; \
    { \
        int c = threadIdx.x; \
        int rbase = threadIdx.y * 4; \
        u64 a1v[4] = {0,0,0,0}, a2v[4] = {0,0,0,0}; \
        _Pragma("unroll") \
        for (int j = 0; j < 14; j++) { \
            ulonglong2 hv = hC[rbase + j][c]; \
            _Pragma("unroll") \
            for (int o = 0; o < 4; o++) { \
                int k = j - o; \
                if (k >= 0 && k < WS) { \
                    a1v[o] = fma2(WSYM(k), hv.x, a1v[o]); \
                    a2v[o] = fma2(WSYM(k), hv.y, a2v[o]); \
                } \
            } \
        } \
        bool colv = (ox0 + c) < (OVAL); \
        _Pragma("unroll") \
        for (int o = 0; o < 4; o++) { \
            if (colv && (oy0 + rbase + o) < (OVAL)) { \
                float2 m = unpack2(a1v[o]); \
                float2 e = unpack2(a2v[o]); \
                float mxx = m.x * m.x, myy = m.y * m.y, mxy = m.x * m.y; \
                float svar = e.x - mxx - myy; \
                float sxy_ = e.y - mxy; \
                const float C1 = 1e-4f, C2 = 9e-4f; \
                float cs = __fdividef(2.f * sxy_ + C2, svar + C2); \
                float ss = __fdividef(2.f * mxy + C1, mxx + myy + C1) * cs; \
                cs_acc += cs; ssim_acc += ss; \
            } \
        } \
    } \
    _Pragma("unroll") \
    for (int o = 16; o > 0; o >>= 1) { \
        ssim_acc += __shfl_down_sync(0xffffffffu, ssim_acc, o); \
        cs_acc   += __shfl_down_sync(0xffffffffu, cs_acc, o); \
    } \
    if (threadIdx.x == 0) { red[threadIdx.y] = ssim_acc; red[8 + threadIdx.y] = cs_acc; } \
    __syncthreads(); \
    if (tid == 0) { \
        float s = 0.f, cc = 0.f; \
        _Pragma("unroll") \
        for (int i = 0; i < 8; i++) { s += red[i]; cc += red[8 + i]; } \
        atomicAdd(&g_ssim_sum[SCALE][nc], s); \
        atomicAdd(&g_cs_sum[SCALE][nc], cc); \
    }

// ======== scale 0: ssim + pooled emission into g_s1 =========================
__global__ __launch_bounds__(256) void ssim_scale0(
    const float* __restrict__ x0, const float* __restrict__ y0,
    const float* __restrict__ win) {
    SSIM_SHARED
    int b = blockIdx.x;
    int nc = b >> 8;
    int r0 = b & 255;
    int by = r0 >> 4, bx = r0 & 15;
    const float* xb = x0 + (size_t)nc * 262144;
    const float* yb = y0 + (size_t)nc * 262144;
    int ox0 = bx * 32, oy0 = by * 32;
    int tid = threadIdx.y * 32 + threadIdx.x;

    SSIM_TAPS

    for (int idx = tid; idx < IN * IN; idx += 256) {
        int r = idx / IN, c = idx - r * IN;
        int gy = oy0 + r, gx = ox0 + c;
        float xv = 0.f, yv = 0.f;
        if (gy < 512 && gx < 512) { xv = xb[gy * 512 + gx]; yv = yb[gy * 512 + gx]; }
        sA[r][c] = pack2(xv, yv);
    }
    __syncthreads();

    SSIM_WP
    SSIM_HORIZ

    // pooled emission: owned 32x32 -> 16x16 of scale-1 (reads stable sA)
    {
        int i = tid >> 4, j = tid & 15;
        u64 s = add2(add2(sA[2*i][2*j], sA[2*i][2*j+1]),
                     add2(sA[2*i+1][2*j], sA[2*i+1][2*j+1]));
        s = mul2(s, pack2(0.25f, 0.25f));
        g_s1[(size_t)nc * 65536 + (size_t)(by * 16 + i) * 256 + (bx * 16 + j)] = s;
    }
    __syncthreads();

    SSIM_VERT_AND_REDUCE(502, 0)
}

// ======== scales 1-4 =========================================================
__global__ __launch_bounds__(256) void ssim_rest(const float* __restrict__ win) {
    SSIM_SHARED
    int b = blockIdx.x;
    int D, O, nc, bx, by, scale;
    const u64* src;
    if (b < 3072)      { scale = 1; D = 256; O = 246; int l = b;        nc = l >> 6; int r = l & 63; by = r >> 3; bx = r & 7; src = g_s1; }
    else if (b < 3840) { scale = 2; D = 128; O = 118; int l = b - 3072; nc = l >> 4; int r = l & 15; by = r >> 2; bx = r & 3; src = g_s2; }
    else if (b < 4032) { scale = 3; D = 64;  O = 54;  int l = b - 3840; nc = l >> 2; int r = l & 3;  by = r >> 1; bx = r & 1; src = g_s3; }
    else               { scale = 4; D = 32;  O = 22;  int l = b - 4032; nc = l;      by = 0;         bx = 0;      src = g_s4; }
    src += (size_t)nc * D * D;
    int ox0 = bx * 32, oy0 = by * 32;
    int tid = threadIdx.y * 32 + threadIdx.x;

    SSIM_TAPS

    for (int idx = tid; idx < IN * IN; idx += 256) {
        int r = idx / IN, c = idx - r * IN;
        int gy = oy0 + r, gx = ox0 + c;
        sA[r][c] = (gy < D && gx < D) ? src[gy * D + gx] : 0ull;
    }
    __syncthreads();

    SSIM_WP
    SSIM_HORIZ
    __syncthreads();

    SSIM_VERT_AND_REDUCE(O, scale)
}

// ======== pool chain: s1 -> s2,s3,s4 =========================================
__global__ __launch_bounds__(256) void pool_rest() {
    __shared__ u64 s2s[32][33];
    __shared__ u64 s3s[16][17];
    int tid = threadIdx.x;
    int b = blockIdx.x;
    int nc = b >> 4;
    int r = b & 15;
    int by = r >> 2, bx = r & 3;
    const u64* s1 = g_s1 + (size_t)nc * 65536;
    u64 quarter = pack2(0.25f, 0.25f);
#pragma unroll
    for (int t = 0; t < 4; t++) {
        int o = tid + t * 256;
        int i = o >> 5, j = o & 31;
        int gr = by * 64 + 2 * i, gc = bx * 64 + 2 * j;
        u64 v = mul2(add2(add2(s1[gr * 256 + gc], s1[gr * 256 + gc + 1]),
                          add2(s1[(gr + 1) * 256 + gc], s1[(gr + 1) * 256 + gc + 1])), quarter);
        s2s[i][j] = v;
        g_s2[(size_t)nc * 16384 + (size_t)(by * 32 + i) * 128 + (bx * 32 + j)] = v;
    }
    __syncthreads();
    {
        int i = tid >> 4, j = tid & 15;
        u64 v = mul2(add2(add2(s2s[2*i][2*j], s2s[2*i][2*j+1]),
                          add2(s2s[2*i+1][2*j], s2s[2*i+1][2*j+1])), quarter);
        s3s[i][j] = v;
        g_s3[(size_t)nc * 4096 + (size_t)(by * 16 + i) * 64 + (bx * 16 + j)] = v;
    }
    __syncthreads();
    if (tid < 64) {
        int i = tid >> 3, j = tid & 7;
        u64 v = mul2(add2(add2(s3s[2*i][2*j], s3s[2*i][2*j+1]),
                          add2(s3s[2*i+1][2*j], s3s[2*i+1][2*j+1])), quarter);
        g_s4[(size_t)nc * 1024 + (size_t)(by * 8 + i) * 32 + (bx * 8 + j)] = v;
    }
}

// ---------------- final ------------------------------------------------------
__global__ void final_kernel(const float* __restrict__ weights, float* __restrict__ out) {
    __shared__ float vals[NC];
    int t = threadIdx.x;
    const int Os[5] = {502, 246, 118, 54, 22};
    if (t < NC) {
        float prod = 1.f;
#pragma unroll
        for (int s = 0; s < 5; s++) {
            float inv = 1.f / ((float)Os[s] * (float)Os[s]);
            float m = (s < 4) ? g_cs_sum[s][t] : g_ssim_sum[s][t];
            m *= inv;
            if (s < 4) m = fmaxf(m, 0.f);
            prod *= powf(m, weights[s]);
        }
        vals[t] = prod;
    }
    __syncthreads();
    if (t == 0) {
        float s = 0.f;
        for (int i = 0; i < NC; i++) s += vals[i];
        out[0] = s / (float)NC;
    }
}

// ---------------- launch -----------------------------------------------------
extern "C" void kernel_launch(void* const* d_in, const int* in_sizes, int n_in,
                              void* d_out, int out_size) {
    const float* x   = (const float*)d_in[0];
    const float* y   = (const float*)d_in[1];
    const float* win = (const float*)d_in[2];
    const float* wts = (const float*)d_in[3];
    float* out = (float*)d_out;

    init_kernel<<<1, 256>>>();
    ssim_scale0<<<12288, dim3(32, 8)>>>(x, y, win);
    pool_rest<<<768, 256>>>();
    ssim_rest<<<4080, dim3(32, 8)>>>(win);
    final_kernel<<<1, 64>>>(wts, out);
}